// round 6
// baseline (speedup 1.0000x reference)
#include <cuda_runtime.h>
#include <math.h>

// Problem constants
#define NB 16384   // batch
#define ND 512     // input dim
#define NH 128     // hidden
#define NH2 256    // 2*hidden
#define NG 18      // genres

#define TM 32      // batch-tile rows per CTA
#define NTHREADS 256

// Shared memory layout (in floats)
#define OFF_X    0        // [32][512]  = 16384
#define OFF_H1   16384    // [32][256]  = 8192 (also stages Wa: 9216 floats, spills into H2 region)
#define OFF_H2   24576    // [32][128]  = 4096
#define OFF_REF  28672    // [32][128]  = 4096
#define OFF_SLAB 32768    // 3 buffers x [16][256] = 12288
#define OFF_W    45056    // [32][18]   = 576
#define SMEM_FLOATS 45632
#define SMEM_BYTES (SMEM_FLOATS * 4)   // 182528 B
#define SLAB_STRIDE 4096               // floats per slab buffer

// ---- cp.async helpers (LDGSTS) ----
__device__ __forceinline__ void cp_async16(float* dst, const float* src) {
    unsigned int s = (unsigned int)__cvta_generic_to_shared(dst);
    asm volatile("cp.async.cg.shared.global [%0], [%1], 16;" :: "r"(s), "l"(src));
}
__device__ __forceinline__ void cp_commit() { asm volatile("cp.async.commit_group;"); }
template<int n> __device__ __forceinline__ void cp_wait() {
    asm volatile("cp.async.wait_group %0;" :: "n"(n));
}

// fp32 register-tiled GEMM accumulate with triple-buffered cp.async weight pipeline:
//   acc[4][N/32] += As[32][K] @ Bg[K x N]   (Bg global, row stride LDB)
// Warp w owns rows 4w..4w+3; lane owns cols lane*(N/32)..+N/32-1.
template<int N, int K, int LDB>
__device__ __forceinline__ void gemm_acc(const float* __restrict__ As,
                                         const float* __restrict__ Bg,
                                         float* __restrict__ slab,
                                         float (&acc)[4][N / 32],
                                         int warp, int lane, int tid)
{
    constexpr int NJ  = N / 32;            // cols per thread
    constexpr int NC4 = N / 4;             // float4s per slab row
    constexpr int NIT = K / 16;            // k-steps
    constexpr int PER = (16 * NC4) / NTHREADS;   // cp.asyncs per thread per slab (2 or 4)

    __syncthreads();   // all previous users of the slab buffers are done

    // preload slab 0 into buffer 0
    {
        #pragma unroll
        for (int p = 0; p < PER; p++) {
            int f = tid + p * NTHREADS;
            int row = f / NC4, c4 = f - row * NC4;
            cp_async16(slab + f * 4, Bg + (size_t)row * LDB + c4 * 4);
        }
        cp_commit();
    }

    for (int it = 0; it < NIT; it++) {
        if (it + 1 < NIT) {
            float* buf = slab + ((it + 1) % 3) * SLAB_STRIDE;
            const float* Bk = Bg + (size_t)(it + 1) * 16 * LDB;
            #pragma unroll
            for (int p = 0; p < PER; p++) {
                int f = tid + p * NTHREADS;
                int row = f / NC4, c4 = f - row * NC4;
                cp_async16(buf + f * 4, Bk + (size_t)row * LDB + c4 * 4);
            }
            cp_commit();
            cp_wait<1>();   // current slab complete; next may remain in flight
        } else {
            cp_wait<0>();
        }
        __syncthreads();    // current slab visible to all threads
        // (triple buffering: next preload targets a buffer last computed-on
        //  two iterations ago, already protected by the intervening syncs)

        const float* buf = slab + (it % 3) * SLAB_STRIDE;
        const int k0 = it * 16;
        const float* a0p = As + (warp * 4 + 0) * K + k0;
        const float* a1p = As + (warp * 4 + 1) * K + k0;
        const float* a2p = As + (warp * 4 + 2) * K + k0;
        const float* a3p = As + (warp * 4 + 3) * K + k0;

        #pragma unroll
        for (int kk = 0; kk < 16; kk++) {
            float a0 = a0p[kk], a1 = a1p[kk], a2 = a2p[kk], a3 = a3p[kk];
            float bv[NJ];
            #pragma unroll
            for (int j = 0; j < NJ; j += 4) {
                float4 v = *(const float4*)(buf + kk * N + lane * NJ + j);
                bv[j] = v.x; bv[j + 1] = v.y; bv[j + 2] = v.z; bv[j + 3] = v.w;
            }
            #pragma unroll
            for (int j = 0; j < NJ; j++) {
                acc[0][j] += a0 * bv[j];
                acc[1][j] += a1 * bv[j];
                acc[2][j] += a2 * bv[j];
                acc[3][j] += a3 * bv[j];
            }
        }
    }
}

__global__ void __launch_bounds__(NTHREADS, 1)
genre_refine_kernel(const float* __restrict__ X,     // [B,D]
                    const float* __restrict__ GV,    // [B,G]
                    const float* __restrict__ W1,    // [G,D,2H]
                    const float* __restrict__ b1,    // [G,2H]
                    const float* __restrict__ W2,    // [G,2H,H]
                    const float* __restrict__ b2,    // [G,H]
                    const float* __restrict__ W3,    // [G,H,H]
                    const float* __restrict__ b3,    // [G,H]
                    const float* __restrict__ Wa,    // [D,G]
                    const float* __restrict__ ba,    // [G]
                    const float* __restrict__ Wagg,  // [D+H,D]
                    const float* __restrict__ bagg,  // [D]
                    float* __restrict__ out)         // [B,D]
{
    extern __shared__ float sm[];
    const int tid  = threadIdx.x;
    const int lane = tid & 31;
    const int warp = tid >> 5;
    const int b0   = blockIdx.x * TM;

    float* Xs   = sm + OFF_X;
    float* h1s  = sm + OFF_H1;
    float* h2s  = sm + OFF_H2;
    float* refs = sm + OFF_REF;
    float* slab = sm + OFF_SLAB;
    float* wf   = sm + OFF_W;

    // ---- load X tile (32x512, contiguous) ----
    {
        const float4* xsrc = (const float4*)(X + (size_t)b0 * ND);
        for (int f = tid; f < TM * ND / 4; f += NTHREADS)
            ((float4*)Xs)[f] = xsrc[f];
    }
    // ---- stage Wa (512x18 = 9216 floats) into h1s region ----
    for (int f = tid; f < ND * NG / 4; f += NTHREADS)
        ((float4*)h1s)[f] = ((const float4*)Wa)[f];
    // ---- zero refinements ----
    for (int f = tid; f < TM * NH; f += NTHREADS)
        refs[f] = 0.0f;
    __syncthreads();

    // ---- attention logits: wf[r*18+g] = X[r] . Wa[:,g] + ba[g] ----
    for (int p = tid; p < TM * NG; p += NTHREADS) {
        int r = p / NG, g = p - r * NG;
        const float* xr = Xs + r * ND;
        float a = ba[g];
        #pragma unroll 8
        for (int k = 0; k < ND; k++)
            a += xr[k] * h1s[k * NG + g];
        wf[p] = a;
    }
    __syncthreads();

    // ---- per-row softmax, then multiply by genre membership ----
    if (tid < TM) {
        int r = tid;
        float m = -1e30f;
        #pragma unroll
        for (int g = 0; g < NG; g++) m = fmaxf(m, wf[r * NG + g]);
        float e[NG];
        float s = 0.0f;
        #pragma unroll
        for (int g = 0; g < NG; g++) { e[g] = expf(wf[r * NG + g] - m); s += e[g]; }
        float inv = 1.0f / s;
        #pragma unroll
        for (int g = 0; g < NG; g++)
            wf[r * NG + g] = e[g] * inv * GV[(size_t)(b0 + r) * NG + g];
    }
    // (next gemm's entry __syncthreads orders this before use)

    // ---- expert loop over genres ----
    for (int g = 0; g < NG; g++) {
        // GEMM1: h1 = relu(X @ W1[g] + b1[g])   [32,512]x[512,256]
        {
            float acc[4][8];
            const float* bias = b1 + g * NH2;
            #pragma unroll
            for (int i = 0; i < 4; i++)
                #pragma unroll
                for (int j = 0; j < 8; j++) acc[i][j] = bias[lane * 8 + j];
            gemm_acc<NH2, ND, NH2>(Xs, W1 + (size_t)g * ND * NH2, slab, acc, warp, lane, tid);
            #pragma unroll
            for (int i = 0; i < 4; i++)
                #pragma unroll
                for (int j = 0; j < 8; j++)
                    h1s[(warp * 4 + i) * NH2 + lane * 8 + j] = fmaxf(acc[i][j], 0.0f);
        }
        // GEMM2: h2 = relu(h1 @ W2[g] + b2[g])  [32,256]x[256,128]
        {
            float acc[4][4];
            const float* bias = b2 + g * NH;
            #pragma unroll
            for (int i = 0; i < 4; i++)
                #pragma unroll
                for (int j = 0; j < 4; j++) acc[i][j] = bias[lane * 4 + j];
            gemm_acc<NH, NH2, NH>(h1s, W2 + (size_t)g * NH2 * NH, slab, acc, warp, lane, tid);
            #pragma unroll
            for (int i = 0; i < 4; i++)
                #pragma unroll
                for (int j = 0; j < 4; j++)
                    h2s[(warp * 4 + i) * NH + lane * 4 + j] = fmaxf(acc[i][j], 0.0f);
        }
        // GEMM3: h3 = h2 @ W3[g] + b3[g] (no relu); refs += w[r,g] * h3
        {
            float acc[4][4];
            const float* bias = b3 + g * NH;
            #pragma unroll
            for (int i = 0; i < 4; i++)
                #pragma unroll
                for (int j = 0; j < 4; j++) acc[i][j] = bias[lane * 4 + j];
            gemm_acc<NH, NH, NH>(h2s, W3 + (size_t)g * NH * NH, slab, acc, warp, lane, tid);
            #pragma unroll
            for (int i = 0; i < 4; i++) {
                float wi = wf[(warp * 4 + i) * NG + g];
                #pragma unroll
                for (int j = 0; j < 4; j++)
                    refs[(warp * 4 + i) * NH + lane * 4 + j] += wi * acc[i][j];
            }
        }
    }

    // ---- final: out = relu([X | refs] @ Wagg + bagg), N=512 in 2 chunks of 256 ----
    for (int chunk = 0; chunk < 2; chunk++) {
        const int cb = chunk * 256;
        float acc[4][8];
        #pragma unroll
        for (int i = 0; i < 4; i++)
            #pragma unroll
            for (int j = 0; j < 8; j++) acc[i][j] = bagg[cb + lane * 8 + j];
        // X part: rows 0..511 of Wagg
        gemm_acc<256, ND, ND>(Xs, Wagg + cb, slab, acc, warp, lane, tid);
        // refinement part: rows 512..639 of Wagg
        gemm_acc<256, NH, ND>(refs, Wagg + (size_t)ND * ND + cb, slab, acc, warp, lane, tid);
        #pragma unroll
        for (int i = 0; i < 4; i++) {
            size_t row = (size_t)(b0 + warp * 4 + i);
            float4 v0, v1;
            v0.x = fmaxf(acc[i][0], 0.0f); v0.y = fmaxf(acc[i][1], 0.0f);
            v0.z = fmaxf(acc[i][2], 0.0f); v0.w = fmaxf(acc[i][3], 0.0f);
            v1.x = fmaxf(acc[i][4], 0.0f); v1.y = fmaxf(acc[i][5], 0.0f);
            v1.z = fmaxf(acc[i][6], 0.0f); v1.w = fmaxf(acc[i][7], 0.0f);
            *(float4*)(out + row * ND + cb + lane * 8)     = v0;
            *(float4*)(out + row * ND + cb + lane * 8 + 4) = v1;
        }
    }
}

extern "C" void kernel_launch(void* const* d_in, const int* in_sizes, int n_in,
                              void* d_out, int out_size)
{
    const float* X    = (const float*)d_in[0];
    const float* GV   = (const float*)d_in[1];
    const float* W1   = (const float*)d_in[2];
    const float* b1   = (const float*)d_in[3];
    const float* W2   = (const float*)d_in[4];
    const float* b2   = (const float*)d_in[5];
    const float* W3   = (const float*)d_in[6];
    const float* b3   = (const float*)d_in[7];
    const float* Wa   = (const float*)d_in[8];
    const float* ba   = (const float*)d_in[9];
    const float* Wagg = (const float*)d_in[10];
    const float* bagg = (const float*)d_in[11];
    float* out = (float*)d_out;

    int nrows = in_sizes[0] / ND;      // batch size
    int grid  = nrows / TM;            // 512 CTAs

    cudaFuncSetAttribute(genre_refine_kernel,
                         cudaFuncAttributeMaxDynamicSharedMemorySize, SMEM_BYTES);
    genre_refine_kernel<<<grid, NTHREADS, SMEM_BYTES>>>(
        X, GV, W1, b1, W2, b2, W3, b3, Wa, ba, Wagg, bagg, out);
}

// round 7
// speedup vs baseline: 1.0028x; 1.0028x over previous
#include <cuda_runtime.h>
#include <math.h>

// Problem constants
#define NB 16384   // batch
#define ND 512     // input dim
#define NH 128     // hidden
#define NH2 256    // 2*hidden
#define NG 18      // genres

#define TM 32      // batch-tile rows per CTA
#define NTHREADS 256

// Shared memory layout (in floats)
#define OFF_X    0        // [32][512]  = 16384
#define OFF_H1   16384    // [32][256]  = 8192 (also stages Wa: 9216 floats, spills into H2 region)
#define OFF_H2   24576    // [32][128]  = 4096
#define OFF_REF  28672    // [32][128]  = 4096
#define OFF_SLAB 32768    // 3 buffers x [16][256] = 12288
#define OFF_W    45056    // [32][18]   = 576
#define SMEM_FLOATS 45632
#define SMEM_BYTES (SMEM_FLOATS * 4)   // 182528 B
#define SLAB_STRIDE 4096               // floats per slab buffer

// ---- cp.async helpers (LDGSTS) ----
__device__ __forceinline__ void cp_async16(float* dst, const float* src) {
    unsigned int s = (unsigned int)__cvta_generic_to_shared(dst);
    asm volatile("cp.async.cg.shared.global [%0], [%1], 16;" :: "r"(s), "l"(src));
}
__device__ __forceinline__ void cp_commit() { asm volatile("cp.async.commit_group;"); }
template<int n> __device__ __forceinline__ void cp_wait() {
    asm volatile("cp.async.wait_group %0;" :: "n"(n));
}

// fp32 register-tiled GEMM accumulate with triple-buffered cp.async weight pipeline:
//   acc[4][N/32] += As[32][K] @ Bg[K x N]   (Bg global, row stride LDB)
// Warp w owns rows 4w..4w+3; lane owns cols lane*(N/32)..+N/32-1.
template<int N, int K, int LDB>
__device__ __forceinline__ void gemm_acc(const float* __restrict__ As,
                                         const float* __restrict__ Bg,
                                         float* __restrict__ slab,
                                         float (&acc)[4][N / 32],
                                         int warp, int lane, int tid)
{
    constexpr int NJ  = N / 32;            // cols per thread
    constexpr int NC4 = N / 4;             // float4s per slab row
    constexpr int NIT = K / 16;            // k-steps
    constexpr int PER = (16 * NC4) / NTHREADS;   // cp.asyncs per thread per slab (2 or 4)

    __syncthreads();   // all previous users of the slab buffers are done

    // preload slab 0 into buffer 0
    {
        #pragma unroll
        for (int p = 0; p < PER; p++) {
            int f = tid + p * NTHREADS;
            int row = f / NC4, c4 = f - row * NC4;
            cp_async16(slab + f * 4, Bg + (size_t)row * LDB + c4 * 4);
        }
        cp_commit();
    }

    for (int it = 0; it < NIT; it++) {
        if (it + 1 < NIT) {
            float* buf = slab + ((it + 1) % 3) * SLAB_STRIDE;
            const float* Bk = Bg + (size_t)(it + 1) * 16 * LDB;
            #pragma unroll
            for (int p = 0; p < PER; p++) {
                int f = tid + p * NTHREADS;
                int row = f / NC4, c4 = f - row * NC4;
                cp_async16(buf + f * 4, Bk + (size_t)row * LDB + c4 * 4);
            }
            cp_commit();
            cp_wait<1>();   // current slab complete; next may remain in flight
        } else {
            cp_wait<0>();
        }
        __syncthreads();    // current slab visible to all threads
        // (triple buffering: next preload targets a buffer last computed-on
        //  two iterations ago, already protected by the intervening syncs)

        const float* buf = slab + (it % 3) * SLAB_STRIDE;
        const int k0 = it * 16;
        const float* a0p = As + (warp * 4 + 0) * K + k0;
        const float* a1p = As + (warp * 4 + 1) * K + k0;
        const float* a2p = As + (warp * 4 + 2) * K + k0;
        const float* a3p = As + (warp * 4 + 3) * K + k0;

        #pragma unroll
        for (int kk = 0; kk < 16; kk++) {
            float a0 = a0p[kk], a1 = a1p[kk], a2 = a2p[kk], a3 = a3p[kk];
            float bv[NJ];
            #pragma unroll
            for (int j = 0; j < NJ; j += 4) {
                float4 v = *(const float4*)(buf + kk * N + lane * NJ + j);
                bv[j] = v.x; bv[j + 1] = v.y; bv[j + 2] = v.z; bv[j + 3] = v.w;
            }
            #pragma unroll
            for (int j = 0; j < NJ; j++) {
                acc[0][j] += a0 * bv[j];
                acc[1][j] += a1 * bv[j];
                acc[2][j] += a2 * bv[j];
                acc[3][j] += a3 * bv[j];
            }
        }
    }
}

__global__ void __launch_bounds__(NTHREADS, 1)
genre_refine_kernel(const float* __restrict__ X,     // [B,D]
                    const float* __restrict__ GV,    // [B,G]
                    const float* __restrict__ W1,    // [G,D,2H]
                    const float* __restrict__ b1,    // [G,2H]
                    const float* __restrict__ W2,    // [G,2H,H]
                    const float* __restrict__ b2,    // [G,H]
                    const float* __restrict__ W3,    // [G,H,H]
                    const float* __restrict__ b3,    // [G,H]
                    const float* __restrict__ Wa,    // [D,G]
                    const float* __restrict__ ba,    // [G]
                    const float* __restrict__ Wagg,  // [D+H,D]
                    const float* __restrict__ bagg,  // [D]
                    float* __restrict__ out)         // [B,D]
{
    extern __shared__ float sm[];
    const int tid  = threadIdx.x;
    const int lane = tid & 31;
    const int warp = tid >> 5;
    const int b0   = blockIdx.x * TM;

    float* Xs   = sm + OFF_X;
    float* h1s  = sm + OFF_H1;
    float* h2s  = sm + OFF_H2;
    float* refs = sm + OFF_REF;
    float* slab = sm + OFF_SLAB;
    float* wf   = sm + OFF_W;

    // ---- load X tile (32x512, contiguous) ----
    {
        const float4* xsrc = (const float4*)(X + (size_t)b0 * ND);
        for (int f = tid; f < TM * ND / 4; f += NTHREADS)
            ((float4*)Xs)[f] = xsrc[f];
    }
    // ---- stage Wa (512x18 = 9216 floats) into h1s region ----
    for (int f = tid; f < ND * NG / 4; f += NTHREADS)
        ((float4*)h1s)[f] = ((const float4*)Wa)[f];
    // ---- zero refinements ----
    for (int f = tid; f < TM * NH; f += NTHREADS)
        refs[f] = 0.0f;
    __syncthreads();

    // ---- attention logits: wf[r*18+g] = X[r] . Wa[:,g] + ba[g] ----
    for (int p = tid; p < TM * NG; p += NTHREADS) {
        int r = p / NG, g = p - r * NG;
        const float* xr = Xs + r * ND;
        float a = ba[g];
        #pragma unroll 8
        for (int k = 0; k < ND; k++)
            a += xr[k] * h1s[k * NG + g];
        wf[p] = a;
    }
    __syncthreads();

    // ---- per-row softmax, then multiply by genre membership ----
    if (tid < TM) {
        int r = tid;
        float m = -1e30f;
        #pragma unroll
        for (int g = 0; g < NG; g++) m = fmaxf(m, wf[r * NG + g]);
        float e[NG];
        float s = 0.0f;
        #pragma unroll
        for (int g = 0; g < NG; g++) { e[g] = expf(wf[r * NG + g] - m); s += e[g]; }
        float inv = 1.0f / s;
        #pragma unroll
        for (int g = 0; g < NG; g++)
            wf[r * NG + g] = e[g] * inv * GV[(size_t)(b0 + r) * NG + g];
    }
    // (next gemm's entry __syncthreads orders this before use)

    // ---- expert loop over genres ----
    for (int g = 0; g < NG; g++) {
        // GEMM1: h1 = relu(X @ W1[g] + b1[g])   [32,512]x[512,256]
        {
            float acc[4][8];
            const float* bias = b1 + g * NH2;
            #pragma unroll
            for (int i = 0; i < 4; i++)
                #pragma unroll
                for (int j = 0; j < 8; j++) acc[i][j] = bias[lane * 8 + j];
            gemm_acc<NH2, ND, NH2>(Xs, W1 + (size_t)g * ND * NH2, slab, acc, warp, lane, tid);
            #pragma unroll
            for (int i = 0; i < 4; i++)
                #pragma unroll
                for (int j = 0; j < 8; j++)
                    h1s[(warp * 4 + i) * NH2 + lane * 8 + j] = fmaxf(acc[i][j], 0.0f);
        }
        // GEMM2: h2 = relu(h1 @ W2[g] + b2[g])  [32,256]x[256,128]
        {
            float acc[4][4];
            const float* bias = b2 + g * NH;
            #pragma unroll
            for (int i = 0; i < 4; i++)
                #pragma unroll
                for (int j = 0; j < 4; j++) acc[i][j] = bias[lane * 4 + j];
            gemm_acc<NH, NH2, NH>(h1s, W2 + (size_t)g * NH2 * NH, slab, acc, warp, lane, tid);
            #pragma unroll
            for (int i = 0; i < 4; i++)
                #pragma unroll
                for (int j = 0; j < 4; j++)
                    h2s[(warp * 4 + i) * NH + lane * 4 + j] = fmaxf(acc[i][j], 0.0f);
        }
        // GEMM3: h3 = h2 @ W3[g] + b3[g] (no relu); refs += w[r,g] * h3
        {
            float acc[4][4];
            const float* bias = b3 + g * NH;
            #pragma unroll
            for (int i = 0; i < 4; i++)
                #pragma unroll
                for (int j = 0; j < 4; j++) acc[i][j] = bias[lane * 4 + j];
            gemm_acc<NH, NH, NH>(h2s, W3 + (size_t)g * NH * NH, slab, acc, warp, lane, tid);
            #pragma unroll
            for (int i = 0; i < 4; i++) {
                float wi = wf[(warp * 4 + i) * NG + g];
                #pragma unroll
                for (int j = 0; j < 4; j++)
                    refs[(warp * 4 + i) * NH + lane * 4 + j] += wi * acc[i][j];
            }
        }
    }

    // ---- final: out = relu([X | refs] @ Wagg + bagg), N=512 in 2 chunks of 256 ----
    for (int chunk = 0; chunk < 2; chunk++) {
        const int cb = chunk * 256;
        float acc[4][8];
        #pragma unroll
        for (int i = 0; i < 4; i++)
            #pragma unroll
            for (int j = 0; j < 8; j++) acc[i][j] = bagg[cb + lane * 8 + j];
        // X part: rows 0..511 of Wagg
        gemm_acc<256, ND, ND>(Xs, Wagg + cb, slab, acc, warp, lane, tid);
        // refinement part: rows 512..639 of Wagg
        gemm_acc<256, NH, ND>(refs, Wagg + (size_t)ND * ND + cb, slab, acc, warp, lane, tid);
        #pragma unroll
        for (int i = 0; i < 4; i++) {
            size_t row = (size_t)(b0 + warp * 4 + i);
            float4 v0, v1;
            v0.x = fmaxf(acc[i][0], 0.0f); v0.y = fmaxf(acc[i][1], 0.0f);
            v0.z = fmaxf(acc[i][2], 0.0f); v0.w = fmaxf(acc[i][3], 0.0f);
            v1.x = fmaxf(acc[i][4], 0.0f); v1.y = fmaxf(acc[i][5], 0.0f);
            v1.z = fmaxf(acc[i][6], 0.0f); v1.w = fmaxf(acc[i][7], 0.0f);
            *(float4*)(out + row * ND + cb + lane * 8)     = v0;
            *(float4*)(out + row * ND + cb + lane * 8 + 4) = v1;
        }
    }
}

extern "C" void kernel_launch(void* const* d_in, const int* in_sizes, int n_in,
                              void* d_out, int out_size)
{
    const float* X    = (const float*)d_in[0];
    const float* GV   = (const float*)d_in[1];
    const float* W1   = (const float*)d_in[2];
    const float* b1   = (const float*)d_in[3];
    const float* W2   = (const float*)d_in[4];
    const float* b2   = (const float*)d_in[5];
    const float* W3   = (const float*)d_in[6];
    const float* b3   = (const float*)d_in[7];
    const float* Wa   = (const float*)d_in[8];
    const float* ba   = (const float*)d_in[9];
    const float* Wagg = (const float*)d_in[10];
    const float* bagg = (const float*)d_in[11];
    float* out = (float*)d_out;

    int nrows = in_sizes[0] / ND;      // batch size
    int grid  = nrows / TM;            // 512 CTAs

    cudaFuncSetAttribute(genre_refine_kernel,
                         cudaFuncAttributeMaxDynamicSharedMemorySize, SMEM_BYTES);
    genre_refine_kernel<<<grid, NTHREADS, SMEM_BYTES>>>(
        X, GV, W1, b1, W2, b2, W3, b3, Wa, ba, Wagg, bagg, out);
}